// round 13
// baseline (speedup 1.0000x reference)
#include <cuda_runtime.h>
#include <cuda_fp16.h>
#include <cstdint>

#define DIN 448
#define HEADS 8
#define HD 56
#define SEQ 8192
#define TOKENS 65536
#define NSLOT 37                      // CTAs per head; grid = 8*37 = 296 = 2/SM
#define MTILES 256                    // 65536 / 256
#define NKT    7                      // 448 / 64
#define GBK    64                     // k-tile depth (halves)

// ---------------- scratch (device globals; no runtime alloc) ---------------
// A-side matrices live in FRAGMENT-BLOB layout (see blob mapping below).
__device__ __half Eh_g[DIN * DIN];
__device__ __half Wh_g[DIN * DIN];
__device__ uint4  Xb_g[(size_t)TOKENS * DIN / 8];   // x  blob (fp16)
__device__ uint4  Yb_g[(size_t)TOKENS * DIN / 8];   // Yn blob (fp16)

// Blob mapping for a [rows, 448] fp16 matrix:
//   row: mi=row>>8, rt=row&255, w=rt>>6, mt=(rt>>4)&3, hi=(rt>>3)&1, g=rt&7
//   col: kt=col>>6, kk=(col>>4)&3, li=(col>>2)&3, p=col&3
//   uint4 index = ((mi*7+kt)*16 + w*4 + kk)*128 + mt*32 + g*4 + li
//   16B unit = {(row g, p01), (row g+8, p01), (row g, p23), (row g+8, p23)}
//   = MMA regs {a0,a1,a2,a3} under the phys-col relabel
//   hw{2li,2li+1}->4li,4li+1 ; hw{2li+8,2li+9}->4li+2,4li+3
//   (same relabel applied to B fragments -> contraction exact).

// ---------------- helpers --------------------------------------------------
#define CP_ASYNC16(dst, src) \
    asm volatile("cp.async.cg.shared.global [%0], [%1], 16;" :: "r"(dst), "l"(src) : "memory")
#define CP_COMMIT() asm volatile("cp.async.commit_group;" ::: "memory")
#define CP_WAIT0()  asm volatile("cp.async.wait_group 0;" ::: "memory")

__device__ __forceinline__ uint32_t smem_u32(const void* p) {
    uint32_t a;
    asm("{ .reg .u64 t; cvta.to.shared.u64 t, %1; cvt.u32.u64 %0, t; }"
        : "=r"(a) : "l"(p));
    return a;
}

// ---------------- persistent GEMM: C[M,448] = A[M,448]*B[448,448]^T --------
// A in fragment blob (gmem, LDG.128 direct to MMA regs — NO smem for A).
// B (56x448 fp16, one head) resident in smem, SW128. 4 warps, warp tile
// 64x56, m16n8k16, f32 acc. DEPTH-2 frag ring (slot = kk&1, distance 2
// kk-blocks) to stay under the register cap. Barrier-free mainloop. 2 CTAs/SM.
// LN=true : LayerNorm epilogue -> Yn fragment blob (g1=gamma, g2=beta)
// LN=false: bias epilogue -> f32 linear out (g1=bias)
#define B_CHUNK (HD * 128)               // 7168 per k-tile
#define GSMEM   (NKT * B_CHUNK)          // 50176
#define KT_U4   2048                     // uint4 per (mi,kt) block = 16*128

template<bool LN>
__global__ __launch_bounds__(128, 2) void gemm_f16(
    const uint4* __restrict__ Ab,    // fragment blob
    const __half* __restrict__ Bg,   // [448,448] row-major [n,k]
    void* __restrict__ Og,
    const float* __restrict__ g1,
    const float* __restrict__ g2)
{
    extern __shared__ char sm[];
    const uint32_t sb = smem_u32(sm);
    const int tid  = threadIdx.x;
    const int warp = tid >> 5, lane = tid & 31;
    const int g  = lane >> 2, li = lane & 3;
    const int hh   = blockIdx.x & 7;
    const int slot = blockIdx.x >> 3;
    const int N0 = hh * HD;
    const int ntile = (slot + NSLOT * 6 < MTILES) ? 7 : 6;

    uint32_t brow[7], swk[4];
    #pragma unroll
    for (int nt = 0; nt < 7; nt++) brow[nt] = (uint32_t)((nt * 8 + g) * 128);
    #pragma unroll
    for (int kk = 0; kk < 4; kk++)
        swk[kk] = (uint32_t)((((2 * kk + (li >> 1)) ^ g) << 4) | ((li & 1) << 3));

    // ---- B panel -> smem (once) ----
    #pragma unroll
    for (int j = 0; j < 25; j++) {
        int o = tid + 128 * j;
        if (o < NKT * HD * 8) {
            int kt = o / (HD * 8), rem = o % (HD * 8);
            int row = rem >> 3, c2 = rem & 7;
            CP_ASYNC16(sb + kt * B_CHUNK + (uint32_t)row * 128
                           + ((uint32_t)((c2 ^ (row & 7)) << 4)),
                       Bg + (size_t)(N0 + row) * DIN + (size_t)kt * GBK + c2 * 8);
        }
    }
    CP_COMMIT();

    // per-thread blob lane offset
    const uint32_t lofs = (uint32_t)(warp * 512 + lane);

    // ---- prologue: frag ring <- kk0, kk1 of first k-tile ----
    uint4 frag[2][4];
    {
        const uint4* ap = Ab + (size_t)slot * 7 * KT_U4 + lofs;
        #pragma unroll
        for (int mt = 0; mt < 4; mt++) frag[0][mt] = ap[mt * 32];
        #pragma unroll
        for (int mt = 0; mt < 4; mt++) frag[1][mt] = ap[128 + mt * 32];
    }

    CP_WAIT0();
    __syncthreads();                      // B visible; only barrier in kernel

    float acc[4][7][4];
    #pragma unroll
    for (int mt = 0; mt < 4; mt++)
        #pragma unroll
        for (int nt = 0; nt < 7; nt++)
            #pragma unroll
            for (int r = 0; r < 4; r++) acc[mt][nt][r] = 0.f;

    int mi = slot;
    for (int ti = 0; ti < ntile; ti++) {
        const uint4* tbase = Ab + (size_t)mi * 7 * KT_U4 + lofs;
        for (int kt = 0; kt < NKT; kt++) {
            const char* sbp = sm + kt * B_CHUNK;
            const bool more = (kt < NKT - 1) || (ti < ntile - 1);
            const uint4* acur = tbase + kt * KT_U4;
            // next kk0/kk1 source: next kt of this tile, or kt0 of next m-tile
            const uint4* anx = (kt < NKT - 1)
                ? acur + KT_U4
                : (more ? Ab + (size_t)(mi + NSLOT) * 7 * KT_U4 + lofs : acur);

            #pragma unroll
            for (int kk = 0; kk < 4; kk++) {
                const uint32_t sw = swk[kk];
                uint2 bv[7];
                #pragma unroll
                for (int nt = 0; nt < 7; nt++)
                    bv[nt] = *(const uint2*)(sbp + brow[nt] + sw);
                #pragma unroll
                for (int mt = 0; mt < 4; mt++) {
                    const uint4 a = frag[kk & 1][mt];
                    #pragma unroll
                    for (int nt = 0; nt < 7; nt++) {
                        asm volatile(
                            "mma.sync.aligned.m16n8k16.row.col.f32.f16.f16.f32 "
                            "{%0,%1,%2,%3}, {%4,%5,%6,%7}, {%8,%9}, {%0,%1,%2,%3};\n"
                            : "+f"(acc[mt][nt][0]), "+f"(acc[mt][nt][1]),
                              "+f"(acc[mt][nt][2]), "+f"(acc[mt][nt][3])
                            : "r"(a.x), "r"(a.y), "r"(a.z), "r"(a.w),
                              "r"(bv[nt].x), "r"(bv[nt].y));
                    }
                }
                // refill this ring slot with data needed 2 kk-blocks ahead
                if (kk < 2) {                          // kk+2 of current kt
                    const uint4* pf = acur + (kk + 2) * 128;
                    #pragma unroll
                    for (int mt = 0; mt < 4; mt++) frag[kk & 1][mt] = pf[mt * 32];
                } else if (more) {                     // kk-2 of next kt
                    const uint4* pf = anx + (kk - 2) * 128;
                    #pragma unroll
                    for (int mt = 0; mt < 4; mt++) frag[kk & 1][mt] = pf[mt * 32];
                }
            }
        }

        // ================= epilogue for m-tile mi ==========================
        if (LN) {
            // LayerNorm over permuted rows; write Yn fragment blob
            #pragma unroll
            for (int mt = 0; mt < 4; mt++) {
                const size_t tok0 = (size_t)mi * 256 + warp * 64 + mt * 16;
                #pragma unroll
                for (int hf = 0; hf < 2; hf++) {
                    const int lo = hf * 2;
                    float s = 0.f;
                    #pragma unroll
                    for (int nt = 0; nt < 7; nt++)
                        s += acc[mt][nt][lo] + acc[mt][nt][lo + 1];
                    #pragma unroll
                    for (int o = 16; o > 0; o >>= 1)
                        s += __shfl_xor_sync(0xffffffffu, s, o);
                    const float mu = s * (1.f / 448.f);
                    float vs = 0.f;
                    #pragma unroll
                    for (int nt = 0; nt < 7; nt++) {
                        float d0 = acc[mt][nt][lo] - mu;
                        float d1 = acc[mt][nt][lo + 1] - mu;
                        vs += d0 * d0 + d1 * d1;
                    }
                    #pragma unroll
                    for (int o = 16; o > 0; o >>= 1)
                        vs += __shfl_xor_sync(0xffffffffu, vs, o);
                    const float rsig = rsqrtf(vs * (1.f / 448.f) + 1e-5f);

                    const size_t tok = tok0 + hf * 8;
                    const size_t R = (tok >> 13) * SEQ + (size_t)hh * 1024
                                   + ((tok & 8191) >> 3);
                    // blob address parts for output row R (byte offsets)
                    const uint32_t mi_o = (uint32_t)(R >> 8), rt = (uint32_t)R & 255;
                    const uint32_t rpart = mi_o * 229376u          // mi*7*16*128*16
                                         + (rt >> 6) * 8192u       // w_o*4*128*16
                                         + (((rt >> 4) & 3) * 512u)// mt_o*32*16
                                         + ((rt & 7) * 64u)        // g_o*4*16
                                         + (((rt >> 3) & 1) * 4u); // hi_o -> .y/.w half
                    char* yb = (char*)Og;
                    #pragma unroll
                    for (int nt = 0; nt < 7; nt++) {
                        const int c = g * 56 + nt * 8 + 2 * li;    // even channel
                        const uint32_t cpart = (uint32_t)(c >> 6) * 32768u   // kt_o*16*128*16
                                             + (uint32_t)((c >> 4) & 3) * 2048u // kk_o*128*16
                                             + (uint32_t)((c >> 2) & 3) * 16u   // li_o
                                             + (uint32_t)((c & 2) << 2);        // p-pair -> +8
                        *(__half2*)(yb + rpart + cpart) = __floats2half2_rn(
                            (acc[mt][nt][lo]     - mu) * rsig * g1[c]     + g2[c],
                            (acc[mt][nt][lo + 1] - mu) * rsig * g1[c + 1] + g2[c + 1]);
                    }
                }
            }
        } else {
            float* Cg = (float*)Og;
            #pragma unroll
            for (int mt = 0; mt < 4; mt++) {
                const size_t r0 = (size_t)mi * 256 + warp * 64 + mt * 16 + g;
                #pragma unroll
                for (int nt = 0; nt < 7; nt++) {
                    const int c0 = N0 + nt * 8 + 2 * li;
                    const float2 bb = *(const float2*)&g1[c0];
                    *(float2*)&Cg[r0 * DIN + c0] =
                        make_float2(acc[mt][nt][0] + bb.x, acc[mt][nt][1] + bb.y);
                    *(float2*)&Cg[(r0 + 8) * DIN + c0] =
                        make_float2(acc[mt][nt][2] + bb.x, acc[mt][nt][3] + bb.y);
                }
            }
        }
        #pragma unroll
        for (int mt = 0; mt < 4; mt++)
            #pragma unroll
            for (int nt = 0; nt < 7; nt++)
                #pragma unroll
                for (int r = 0; r < 4; r++) acc[mt][nt][r] = 0.f;
        mi += NSLOT;
    }
}

// ---------------- x (f32) -> fragment blob (fp16) --------------------------
// One thread per 16B blob unit; unit id == blob uint4 index (coalesced STG).
__global__ void conv_blob(const float* __restrict__ X, uint4* __restrict__ Out,
                          int nunits) {
    int id = blockIdx.x * blockDim.x + threadIdx.x;
    if (id >= nunits) return;
    const int lane = id & 31, li = lane & 3, gg = lane >> 2;
    const int mt = (id >> 5) & 3, kk = (id >> 7) & 3, w = (id >> 9) & 3;
    const int ktmi = id >> 11;
    const int mi = ktmi / 7, kt = ktmi - mi * 7;
    const int r0 = mi * 256 + w * 64 + mt * 16 + gg;
    const int c0 = kt * 64 + kk * 16 + li * 4;
    const float4 v0 = *(const float4*)(X + (size_t)r0 * DIN + c0);
    const float4 v1 = *(const float4*)(X + (size_t)(r0 + 8) * DIN + c0);
    __half2 h0 = __floats2half2_rn(v0.x, v0.y);   // row g,   p01
    __half2 h1 = __floats2half2_rn(v1.x, v1.y);   // row g+8, p01
    __half2 h2 = __floats2half2_rn(v0.z, v0.w);   // row g,   p23
    __half2 h3 = __floats2half2_rn(v1.z, v1.w);   // row g+8, p23
    uint4 o;
    o.x = *(uint32_t*)&h0; o.y = *(uint32_t*)&h1;
    o.z = *(uint32_t*)&h2; o.w = *(uint32_t*)&h3;
    Out[id] = o;
}

// ---------------- f32 -> fp16 linear conversion (for W) --------------------
__global__ void conv_h(const float4* __restrict__ src, __half2* __restrict__ dst, int n4) {
    int i = blockIdx.x * blockDim.x + threadIdx.x;
    if (i < n4) {
        float4 v = src[i];
        dst[2 * i]     = __floats2half2_rn(v.x, v.y);
        dst[2 * i + 1] = __floats2half2_rn(v.z, v.w);
    }
}

// ---------------- E_h = C_h * M^T * A_h^T * B_h  (-> fp16) -----------------
__global__ void computeE_k(const float* __restrict__ A, const float* __restrict__ B,
                           const float* __restrict__ C) {
    __shared__ float G[HD * HD], Cs[HD * HD], F[7 * HD];
    const int h = blockIdx.x, oc = blockIdx.y;
    const int tid = threadIdx.x;     // 448 threads
    for (int i = tid; i < HD * HD; i += 448) {
        G[i]  = A[h * HD * HD + i];
        Cs[i] = C[h * HD * HD + i];
    }
    __syncthreads();
    if (tid < HD) {
        #pragma unroll
        for (int e = HD - 2; e >= 0; e--) G[tid * HD + e] += G[tid * HD + e + 1];
    }
    __syncthreads();
    if (tid < 7 * HD) {
        int ol = tid / HD, d = tid % HD;
        float s = 0.f;
        #pragma unroll
        for (int e = 0; e < HD; e++) s += Cs[(oc * 7 + ol) * HD + e] * G[d * HD + e];
        F[ol * HD + d] = s;
    }
    __syncthreads();
    const int i = tid;
    float acc[7] = {0, 0, 0, 0, 0, 0, 0};
    for (int d = 0; d < HD; d++) {
        float b = B[(size_t)(h * HD + d) * DIN + i];
        #pragma unroll
        for (int ol = 0; ol < 7; ol++) acc[ol] += F[ol * HD + d] * b;
    }
    #pragma unroll
    for (int ol = 0; ol < 7; ol++)
        Eh_g[(size_t)(h * HD + oc * 7 + ol) * DIN + i] = __float2half_rn(acc[ol]);
}

// ---------------------------------------------------------------------------
extern "C" void kernel_launch(void* const* d_in, const int* in_sizes, int n_in,
                              void* d_out, int out_size) {
    const float* x     = (const float*)d_in[0];
    const float* A     = (const float*)d_in[1];
    const float* B     = (const float*)d_in[2];
    const float* C     = (const float*)d_in[3];
    const float* gamma = (const float*)d_in[4];
    const float* beta  = (const float*)d_in[5];
    const float* W     = (const float*)d_in[6];
    const float* bias  = (const float*)d_in[7];
    float* out = (float*)d_out;

    __half *Eh_p, *Wh_p;
    uint4 *Xb_p, *Yb_p;
    cudaGetSymbolAddress((void**)&Eh_p, Eh_g);
    cudaGetSymbolAddress((void**)&Wh_p, Wh_g);
    cudaGetSymbolAddress((void**)&Xb_p, Xb_g);
    cudaGetSymbolAddress((void**)&Yb_p, Yb_g);

    cudaFuncSetAttribute(gemm_f16<true>,
                         cudaFuncAttributeMaxDynamicSharedMemorySize, GSMEM);
    cudaFuncSetAttribute(gemm_f16<false>,
                         cudaFuncAttributeMaxDynamicSharedMemorySize, GSMEM);

    const int nunits = TOKENS * DIN / 8;          // 3,670,016
    conv_blob<<<nunits / 256, 256>>>(x, Xb_p, nunits);
    conv_h<<<196, 256>>>((const float4*)W, (__half2*)Wh_p, 50176);
    computeE_k<<<dim3(HEADS, 8), DIN>>>(A, B, C);

    // GEMM1 (+LN, permuted) : x-blob @ E^T -> Yn blob
    gemm_f16<true><<<HEADS * NSLOT, 128, GSMEM>>>(Xb_p, Eh_p, Yb_p, gamma, beta);
    // GEMM2 (+bias)         : Yn-blob @ W^T -> out (f32 linear)
    gemm_f16<false><<<HEADS * NSLOT, 128, GSMEM>>>(Yb_p, Wh_p, out, bias, nullptr);
}

// round 14
// speedup vs baseline: 1.2877x; 1.2877x over previous
#include <cuda_runtime.h>
#include <cuda_fp16.h>
#include <cstdint>

#define DIN 448
#define HEADS 8
#define HD 56
#define SEQ 8192
#define TOKENS 65536
#define NSLOT 37                      // CTAs per head; grid = 8*37 = 296 = 2/SM
#define MTILES 256                    // 65536 / 256
#define NKT    7                      // 448 / 64
#define GBK    64                     // k-tile depth (halves)

// ---------------- scratch (device globals; no runtime alloc) ---------------
// A-side matrices live in FRAGMENT-BLOB layout (see blob mapping below).
__device__ __half Eh_g[DIN * DIN];
__device__ __half Wh_g[DIN * DIN];
__device__ uint4  Xb_g[(size_t)TOKENS * DIN / 8];   // x  blob (fp16)
__device__ uint4  Yb_g[(size_t)TOKENS * DIN / 8];   // Yn blob (fp16)

// Blob mapping for a [rows, 448] fp16 matrix:
//   row: mi=row>>8, rt=row&255, w=rt>>6, mt=(rt>>4)&3, hi=(rt>>3)&1, g=rt&7
//   col: kt=col>>6, kk=(col>>4)&3, li=(col>>2)&3, p=col&3
//   uint4 index = ((mi*7+kt)*16 + w*4 + kk)*128 + mt*32 + g*4 + li
//   16B unit = {(row g, p01), (row g+8, p01), (row g, p23), (row g+8, p23)}
//   = MMA regs {a0,a1,a2,a3} under the phys-col relabel
//   hw{2li,2li+1}->4li,4li+1 ; hw{2li+8,2li+9}->4li+2,4li+3
//   (same relabel applied to B fragments -> contraction exact).

// ---------------- helpers --------------------------------------------------
#define CP_ASYNC16(dst, src) \
    asm volatile("cp.async.cg.shared.global [%0], [%1], 16;" :: "r"(dst), "l"(src) : "memory")
#define CP_COMMIT() asm volatile("cp.async.commit_group;" ::: "memory")
#define CP_WAIT0()  asm volatile("cp.async.wait_group 0;" ::: "memory")
#define PREFETCH_L2(p) \
    asm volatile("prefetch.global.L2 [%0];" :: "l"(p))

__device__ __forceinline__ uint32_t smem_u32(const void* p) {
    uint32_t a;
    asm("{ .reg .u64 t; cvta.to.shared.u64 t, %1; cvt.u32.u64 %0, t; }"
        : "=r"(a) : "l"(p));
    return a;
}

// ---------------- persistent GEMM: C[M,448] = A[M,448]*B[448,448]^T --------
// A in fragment blob (gmem, LDG.128 direct to MMA regs — NO smem for A).
// B (56x448 fp16, one head) resident in smem, SW128. 4 warps, warp tile
// 64x56, m16n8k16, f32 acc. Depth-4 frag ring (slot = kk, distance one full
// k-tile) + L2 PREFETCH of the A tile two k-tiles ahead. Barrier-free
// mainloop. 2 CTAs/SM.
// LN=true : LayerNorm epilogue -> Yn fragment blob (g1=gamma, g2=beta)
// LN=false: bias epilogue -> f32 linear out (g1=bias)
#define B_CHUNK (HD * 128)               // 7168 per k-tile
#define GSMEM   (NKT * B_CHUNK)          // 50176
#define KT_U4   2048                     // uint4 per (mi,kt) block = 16*128

template<bool LN>
__global__ __launch_bounds__(128, 2) void gemm_f16(
    const uint4* __restrict__ Ab,    // fragment blob
    const __half* __restrict__ Bg,   // [448,448] row-major [n,k]
    void* __restrict__ Og,
    const float* __restrict__ g1,
    const float* __restrict__ g2)
{
    extern __shared__ char sm[];
    const uint32_t sb = smem_u32(sm);
    const int tid  = threadIdx.x;
    const int warp = tid >> 5, lane = tid & 31;
    const int g  = lane >> 2, li = lane & 3;
    const int hh   = blockIdx.x & 7;
    const int slot = blockIdx.x >> 3;
    const int N0 = hh * HD;
    const int ntile = (slot + NSLOT * 6 < MTILES) ? 7 : 6;

    uint32_t brow[7], swk[4];
    #pragma unroll
    for (int nt = 0; nt < 7; nt++) brow[nt] = (uint32_t)((nt * 8 + g) * 128);
    #pragma unroll
    for (int kk = 0; kk < 4; kk++)
        swk[kk] = (uint32_t)((((2 * kk + (li >> 1)) ^ g) << 4) | ((li & 1) << 3));

    // ---- B panel -> smem (once) ----
    #pragma unroll
    for (int j = 0; j < 25; j++) {
        int o = tid + 128 * j;
        if (o < NKT * HD * 8) {
            int kt = o / (HD * 8), rem = o % (HD * 8);
            int row = rem >> 3, c2 = rem & 7;
            CP_ASYNC16(sb + kt * B_CHUNK + (uint32_t)row * 128
                           + ((uint32_t)((c2 ^ (row & 7)) << 4)),
                       Bg + (size_t)(N0 + row) * DIN + (size_t)kt * GBK + c2 * 8);
        }
    }
    CP_COMMIT();

    // ---- prologue: prefetch first k-tile's A fragments (ring slot = kk) ----
    uint4 frag[4][4];
    {
        const uint4* ap = Ab + ((size_t)(slot * 7 + 0) * 16 + warp * 4) * 128 + lane;
        #pragma unroll
        for (int kk = 0; kk < 4; kk++)
            #pragma unroll
            for (int mt = 0; mt < 4; mt++)
                frag[kk][mt] = ap[kk * 128 + mt * 32];
    }

    CP_WAIT0();
    __syncthreads();                      // B visible; only barrier in kernel

    float acc[4][7][4];
    #pragma unroll
    for (int mt = 0; mt < 4; mt++)
        #pragma unroll
        for (int nt = 0; nt < 7; nt++)
            #pragma unroll
            for (int r = 0; r < 4; r++) acc[mt][nt][r] = 0.f;

    int mi = slot;
    for (int ti = 0; ti < ntile; ti++) {
        for (int kt = 0; kt < NKT; kt++) {
            const char* sbp = sm + kt * B_CHUNK;
            const bool more = (kt < NKT - 1) || (ti < ntile - 1);
            const int nmi = (kt < NKT - 1) ? mi : mi + NSLOT;
            const int nkt = (kt < NKT - 1) ? kt + 1 : 0;
            const uint4* anx = Ab + ((size_t)(nmi * 7 + nkt) * 16 + warp * 4) * 128 + lane;

            // L2 prefetch: A region for k-tile t+2 (this warp's 8KB segment)
            {
                int p2mi, p2kt;
                bool pok = true;
                if (kt + 2 < NKT)            { p2mi = mi;         p2kt = kt + 2; }
                else if (ti + 1 < ntile)     { p2mi = mi + NSLOT; p2kt = kt + 2 - NKT; }
                else                         { p2mi = mi; p2kt = 0; pok = false; }
                if (pok) {
                    const char* pfp = (const char*)(Ab
                        + ((size_t)(p2mi * 7 + p2kt) * 16 + warp * 4) * 128)
                        + (uint32_t)lane * 256;
                    PREFETCH_L2(pfp);
                    PREFETCH_L2(pfp + 128);
                }
            }

            #pragma unroll
            for (int kk = 0; kk < 4; kk++) {
                const uint32_t sw = swk[kk];
                uint2 bv[7];
                #pragma unroll
                for (int nt = 0; nt < 7; nt++)
                    bv[nt] = *(const uint2*)(sbp + brow[nt] + sw);
                #pragma unroll
                for (int mt = 0; mt < 4; mt++) {
                    const uint4 a = frag[kk][mt];
                    #pragma unroll
                    for (int nt = 0; nt < 7; nt++) {
                        asm volatile(
                            "mma.sync.aligned.m16n8k16.row.col.f32.f16.f16.f32 "
                            "{%0,%1,%2,%3}, {%4,%5,%6,%7}, {%8,%9}, {%0,%1,%2,%3};\n"
                            : "+f"(acc[mt][nt][0]), "+f"(acc[mt][nt][1]),
                              "+f"(acc[mt][nt][2]), "+f"(acc[mt][nt][3])
                            : "r"(a.x), "r"(a.y), "r"(a.z), "r"(a.w),
                              "r"(bv[nt].x), "r"(bv[nt].y));
                    }
                }
                if (more) {
                    #pragma unroll
                    for (int mt = 0; mt < 4; mt++)
                        frag[kk][mt] = anx[kk * 128 + mt * 32];
                }
            }
        }

        // ================= epilogue for m-tile mi ==========================
        if (LN) {
            // LayerNorm over permuted rows; write Yn fragment blob
            #pragma unroll
            for (int mt = 0; mt < 4; mt++) {
                const size_t tok0 = (size_t)mi * 256 + warp * 64 + mt * 16;
                #pragma unroll
                for (int hf = 0; hf < 2; hf++) {
                    const int lo = hf * 2;
                    float s = 0.f;
                    #pragma unroll
                    for (int nt = 0; nt < 7; nt++)
                        s += acc[mt][nt][lo] + acc[mt][nt][lo + 1];
                    #pragma unroll
                    for (int o = 16; o > 0; o >>= 1)
                        s += __shfl_xor_sync(0xffffffffu, s, o);
                    const float mu = s * (1.f / 448.f);
                    float vs = 0.f;
                    #pragma unroll
                    for (int nt = 0; nt < 7; nt++) {
                        float d0 = acc[mt][nt][lo] - mu;
                        float d1 = acc[mt][nt][lo + 1] - mu;
                        vs += d0 * d0 + d1 * d1;
                    }
                    #pragma unroll
                    for (int o = 16; o > 0; o >>= 1)
                        vs += __shfl_xor_sync(0xffffffffu, vs, o);
                    const float rsig = rsqrtf(vs * (1.f / 448.f) + 1e-5f);

                    const size_t tok = tok0 + hf * 8;
                    const size_t R = (tok >> 13) * SEQ + (size_t)hh * 1024
                                   + ((tok & 8191) >> 3);
                    // blob address parts for output row R (byte offsets)
                    const uint32_t mi_o = (uint32_t)(R >> 8), rt = (uint32_t)R & 255;
                    const uint32_t rpart = mi_o * 229376u          // mi*7*16*128*16
                                         + (rt >> 6) * 8192u       // w_o*4*128*16
                                         + (((rt >> 4) & 3) * 512u)// mt_o*32*16
                                         + ((rt & 7) * 64u)        // g_o*4*16
                                         + (((rt >> 3) & 1) * 4u); // hi_o -> .y/.w half
                    char* yb = (char*)Og;
                    #pragma unroll
                    for (int nt = 0; nt < 7; nt++) {
                        const int c = g * 56 + nt * 8 + 2 * li;    // even channel
                        const uint32_t cpart = (uint32_t)(c >> 6) * 32768u   // kt_o*16*128*16
                                             + (uint32_t)((c >> 4) & 3) * 2048u // kk_o*128*16
                                             + (uint32_t)((c >> 2) & 3) * 16u   // li_o
                                             + (uint32_t)((c & 2) << 2);        // p-pair -> +8
                        *(__half2*)(yb + rpart + cpart) = __floats2half2_rn(
                            (acc[mt][nt][lo]     - mu) * rsig * g1[c]     + g2[c],
                            (acc[mt][nt][lo + 1] - mu) * rsig * g1[c + 1] + g2[c + 1]);
                    }
                }
            }
        } else {
            float* Cg = (float*)Og;
            #pragma unroll
            for (int mt = 0; mt < 4; mt++) {
                const size_t r0 = (size_t)mi * 256 + warp * 64 + mt * 16 + g;
                #pragma unroll
                for (int nt = 0; nt < 7; nt++) {
                    const int c0 = N0 + nt * 8 + 2 * li;
                    const float2 bb = *(const float2*)&g1[c0];
                    *(float2*)&Cg[r0 * DIN + c0] =
                        make_float2(acc[mt][nt][0] + bb.x, acc[mt][nt][1] + bb.y);
                    *(float2*)&Cg[(r0 + 8) * DIN + c0] =
                        make_float2(acc[mt][nt][2] + bb.x, acc[mt][nt][3] + bb.y);
                }
            }
        }
        #pragma unroll
        for (int mt = 0; mt < 4; mt++)
            #pragma unroll
            for (int nt = 0; nt < 7; nt++)
                #pragma unroll
                for (int r = 0; r < 4; r++) acc[mt][nt][r] = 0.f;
        mi += NSLOT;
    }
}

// ---------------- x (f32) -> fragment blob (fp16) --------------------------
// One thread per 16B blob unit; unit id == blob uint4 index (coalesced STG).
__global__ void conv_blob(const float* __restrict__ X, uint4* __restrict__ Out,
                          int nunits) {
    int id = blockIdx.x * blockDim.x + threadIdx.x;
    if (id >= nunits) return;
    const int lane = id & 31, li = lane & 3, gg = lane >> 2;
    const int mt = (id >> 5) & 3, kk = (id >> 7) & 3, w = (id >> 9) & 3;
    const int ktmi = id >> 11;
    const int mi = ktmi / 7, kt = ktmi - mi * 7;
    const int r0 = mi * 256 + w * 64 + mt * 16 + gg;
    const int c0 = kt * 64 + kk * 16 + li * 4;
    const float4 v0 = *(const float4*)(X + (size_t)r0 * DIN + c0);
    const float4 v1 = *(const float4*)(X + (size_t)(r0 + 8) * DIN + c0);
    __half2 h0 = __floats2half2_rn(v0.x, v0.y);   // row g,   p01
    __half2 h1 = __floats2half2_rn(v1.x, v1.y);   // row g+8, p01
    __half2 h2 = __floats2half2_rn(v0.z, v0.w);   // row g,   p23
    __half2 h3 = __floats2half2_rn(v1.z, v1.w);   // row g+8, p23
    uint4 o;
    o.x = *(uint32_t*)&h0; o.y = *(uint32_t*)&h1;
    o.z = *(uint32_t*)&h2; o.w = *(uint32_t*)&h3;
    Out[id] = o;
}

// ---------------- f32 -> fp16 linear conversion (for W) --------------------
__global__ void conv_h(const float4* __restrict__ src, __half2* __restrict__ dst, int n4) {
    int i = blockIdx.x * blockDim.x + threadIdx.x;
    if (i < n4) {
        float4 v = src[i];
        dst[2 * i]     = __floats2half2_rn(v.x, v.y);
        dst[2 * i + 1] = __floats2half2_rn(v.z, v.w);
    }
}

// ---------------- E_h = C_h * M^T * A_h^T * B_h  (-> fp16) -----------------
__global__ void computeE_k(const float* __restrict__ A, const float* __restrict__ B,
                           const float* __restrict__ C) {
    __shared__ float G[HD * HD], Cs[HD * HD], F[7 * HD];
    const int h = blockIdx.x, oc = blockIdx.y;
    const int tid = threadIdx.x;     // 448 threads
    for (int i = tid; i < HD * HD; i += 448) {
        G[i]  = A[h * HD * HD + i];
        Cs[i] = C[h * HD * HD + i];
    }
    __syncthreads();
    if (tid < HD) {
        #pragma unroll
        for (int e = HD - 2; e >= 0; e--) G[tid * HD + e] += G[tid * HD + e + 1];
    }
    __syncthreads();
    if (tid < 7 * HD) {
        int ol = tid / HD, d = tid % HD;
        float s = 0.f;
        #pragma unroll
        for (int e = 0; e < HD; e++) s += Cs[(oc * 7 + ol) * HD + e] * G[d * HD + e];
        F[ol * HD + d] = s;
    }
    __syncthreads();
    const int i = tid;
    float acc[7] = {0, 0, 0, 0, 0, 0, 0};
    for (int d = 0; d < HD; d++) {
        float b = B[(size_t)(h * HD + d) * DIN + i];
        #pragma unroll
        for (int ol = 0; ol < 7; ol++) acc[ol] += F[ol * HD + d] * b;
    }
    #pragma unroll
    for (int ol = 0; ol < 7; ol++)
        Eh_g[(size_t)(h * HD + oc * 7 + ol) * DIN + i] = __float2half_rn(acc[ol]);
}

// ---------------------------------------------------------------------------
extern "C" void kernel_launch(void* const* d_in, const int* in_sizes, int n_in,
                              void* d_out, int out_size) {
    const float* x     = (const float*)d_in[0];
    const float* A     = (const float*)d_in[1];
    const float* B     = (const float*)d_in[2];
    const float* C     = (const float*)d_in[3];
    const float* gamma = (const float*)d_in[4];
    const float* beta  = (const float*)d_in[5];
    const float* W     = (const float*)d_in[6];
    const float* bias  = (const float*)d_in[7];
    float* out = (float*)d_out;

    __half *Eh_p, *Wh_p;
    uint4 *Xb_p, *Yb_p;
    cudaGetSymbolAddress((void**)&Eh_p, Eh_g);
    cudaGetSymbolAddress((void**)&Wh_p, Wh_g);
    cudaGetSymbolAddress((void**)&Xb_p, Xb_g);
    cudaGetSymbolAddress((void**)&Yb_p, Yb_g);

    cudaFuncSetAttribute(gemm_f16<true>,
                         cudaFuncAttributeMaxDynamicSharedMemorySize, GSMEM);
    cudaFuncSetAttribute(gemm_f16<false>,
                         cudaFuncAttributeMaxDynamicSharedMemorySize, GSMEM);

    const int nunits = TOKENS * DIN / 8;          // 3,670,016
    conv_blob<<<nunits / 256, 256>>>(x, Xb_p, nunits);
    conv_h<<<196, 256>>>((const float4*)W, (__half2*)Wh_p, 50176);
    computeE_k<<<dim3(HEADS, 8), DIN>>>(A, B, C);

    // GEMM1 (+LN, permuted) : x-blob @ E^T -> Yn blob
    gemm_f16<true><<<HEADS * NSLOT, 128, GSMEM>>>(Xb_p, Eh_p, Yb_p, gamma, beta);
    // GEMM2 (+bias)         : Yn-blob @ W^T -> out (f32 linear)
    gemm_f16<false><<<HEADS * NSLOT, 128, GSMEM>>>(Yb_p, Wh_p, out, bias, nullptr);
}